// round 14
// baseline (speedup 1.0000x reference)
#include <cuda_runtime.h>
#include <cstdint>

#define N_BAGS 4
#define P_PATCH 20000
#define DIN 1024
#define ROWS (N_BAGS*P_PATCH)   /* 80000 */
#define M_TILE 128
#define NTILES (ROWS/M_TILE)    /* 625, exact */
#define GRID1 456               /* 3 CTAs/SM x 152 SMs: persistent */
#define NB 72                   /* 64 proj cols + 8 centroid cols */
#define XS_STRIDE 36
#define EP_STRIDE 76
#define BUF_FLOATS (M_TILE*XS_STRIDE + 32*NB)   /* 4608 + 2304 = 6912 */
/* part(2048) + x2p(128) + c2s(8) + sAssign(128B = 32 floats) */
#define SMEM_FLOATS (2*BUF_FLOATS + 2048 + 128 + 8 + 32)
#define SMEM_BYTES (SMEM_FLOATS * 4)            /* 64160 */

/* scratch (no allocation allowed). Zero at module load; the tail epilogue
   re-zeroes everything dirtied, so each call sees zeros (invariant). */
__device__ float g_S[32*64];
__device__ int   g_counts[32];
__device__ int   g_done;
__device__ int   g_next;

static __device__ __forceinline__ uint32_t tf32_bits(float f){
    uint32_t u; asm("cvt.rna.tf32.f32 %0, %1;" : "=r"(u) : "f"(f)); return u;
}

static __device__ __forceinline__ void mma8(float* c,
    uint32_t a0, uint32_t a1, uint32_t a2, uint32_t a3, uint32_t b0, uint32_t b1)
{
    asm volatile(
      "mma.sync.aligned.m16n8k8.row.col.f32.tf32.tf32.f32 "
      "{%0,%1,%2,%3},{%4,%5,%6,%7},{%8,%9},{%0,%1,%2,%3};\n"
      : "+f"(c[0]), "+f"(c[1]), "+f"(c[2]), "+f"(c[3])
      : "r"(a0), "r"(a1), "r"(a2), "r"(a3), "r"(b0), "r"(b1));
}

static __device__ __forceinline__ void cpa16(float* dst, const float* src){
    uint32_t d = (uint32_t)__cvta_generic_to_shared(dst);
    asm volatile("cp.async.cg.shared.global [%0], [%1], 16;\n" :: "r"(d), "l"(src));
}
static __device__ __forceinline__ void cpa4(float* dst, const float* src){
    uint32_t d = (uint32_t)__cvta_generic_to_shared(dst);
    asm volatile("cp.async.ca.shared.global [%0], [%1], 4;\n" :: "r"(d), "l"(src));
}
#define CP_COMMIT   asm volatile("cp.async.commit_group;\n" ::: "memory")
#define CP_WAIT0    asm volatile("cp.async.wait_group 0;\n" ::: "memory")

/* ------------------------------------------------------------------ */
/* Persistent kernel: dynamic tile grabber; per tile: cp.async double */
/* buffered xp = relu(x@Wpre+b) (dual store), hard assignment, fused  */
/* cluster pooling. 2-D warp grid (4 rowgroups x 2 colgroups) halves  */
/* B smem re-reads; one barrier per chunk. Last CTA runs the MLP tail.*/
/* ------------------------------------------------------------------ */
__global__ __launch_bounds__(256, 3) void k1(
    const float* __restrict__ x, const float* __restrict__ centroids,
    const float* __restrict__ W_pre, const float* __restrict__ b_pre,
    const float* __restrict__ W_a1, const float* __restrict__ b_a1,
    const float* __restrict__ W_a2, const float* __restrict__ b_a2,
    const float* __restrict__ W_out, const float* __restrict__ b_out,
    float* __restrict__ O1, float* __restrict__ O2, float* __restrict__ out)
{
    extern __shared__ float sp[];
    float* ep   = sp;                       /* [128][76] epilogue (aliases bufs) */
    float* part = sp + 2*BUF_FLOATS;        /* [8][8][32] pooling partials */
    float* x2p  = part + 2048;              /* [128] per-row x^2 */
    float* c2s  = x2p + 128;                /* [8] centroid norms */
    unsigned char* sAssign = (unsigned char*)(c2s + 8);  /* [128] bytes */
    __shared__ int sTile, sLast;

    const int t = threadIdx.x, warp = t >> 5, lane = t & 31;
    const int gid = lane >> 2, tig = lane & 3;
    const int lrow = t >> 1, lcb = (t & 1) * 16;
    const int wrow = warp * 16;             /* pooling row group */
    const int rg = warp >> 1, cg = warp & 1; /* MMA warp grid */
    const int rbase = rg * 32;

    /* exact fp32 centroid norms (once per CTA): warp w -> centroid w */
    {
        float s = 0.f;
        const float* c = centroids + (size_t)warp * DIN;
        #pragma unroll
        for (int d = 0; d < DIN/32; d++) { float v = c[lane + 32*d]; s = fmaf(v, v, s); }
        #pragma unroll
        for (int o = 16; o; o >>= 1) s += __shfl_xor_sync(0xffffffffu, s, o);
        if (lane == 0) c2s[warp] = s;
    }

    const float* cg0c = centroids + (size_t)warp * DIN + lane;

    /* =================== persistent tile loop =================== */
    for (;;) {
        if (t == 0) sTile = atomicAdd(&g_next, 1);
        __syncthreads();
        const int tile = sTile;
        if (tile >= NTILES) break;
        const int rowBase = tile * M_TILE;

        float acc[5][2][4];
        #pragma unroll
        for (int nt = 0; nt < 5; nt++)
            #pragma unroll
            for (int m = 0; m < 2; m++)
                acc[nt][m][0]=acc[nt][m][1]=acc[nt][m][2]=acc[nt][m][3]=0.f;
        float x2r[4] = {0.f, 0.f, 0.f, 0.f};

        const float* xg0 = x + (size_t)(rowBase + lrow) * DIN + lcb;

        /* prefetch chunk 0 into buffer 0 */
        {
            float* xs = sp, * Bs = sp + M_TILE*XS_STRIDE;
            #pragma unroll
            for (int j = 0; j < 4; j++)
                cpa16(xs + lrow*XS_STRIDE + lcb + 4*j, xg0 + 4*j);
            #pragma unroll
            for (int j = 0; j < 2; j++) {
                int idx = t + 256*j, r = idx >> 4, c4 = idx & 15;
                cpa16(Bs + r*NB + c4*4, W_pre + (size_t)r*64 + c4*4);
            }
            cpa4(Bs + lane*NB + 64 + warp, cg0c);
            CP_COMMIT;
        }

        #pragma unroll 1
        for (int i = 0; i < 32; i++) {
            CP_WAIT0;          /* chunk i landed (only outstanding group) */
            __syncthreads();   /* data visible; prev-chunk reads complete */
            if (i < 31) {      /* prefetch i+1 into the other buffer */
                const int kcEl = (i + 1) * 32;
                float* xs = sp + ((i+1)&1)*BUF_FLOATS, * Bs = xs + M_TILE*XS_STRIDE;
                #pragma unroll
                for (int j = 0; j < 4; j++)
                    cpa16(xs + lrow*XS_STRIDE + lcb + 4*j, xg0 + kcEl + 4*j);
                #pragma unroll
                for (int j = 0; j < 2; j++) {
                    int idx = t + 256*j, r = idx >> 4, c4 = idx & 15;
                    cpa16(Bs + r*NB + c4*4, W_pre + (size_t)(kcEl + r)*64 + c4*4);
                }
                cpa4(Bs + lane*NB + 64 + warp, cg0c + kcEl);
                CP_COMMIT;
            }
            /* MMA on buffer i&1: warp = 32 rows (2 M-tiles) x colgroup */
            {
                const float* xs = sp + (i&1)*BUF_FLOATS;
                const float* Bs = xs + M_TILE*XS_STRIDE;
                #pragma unroll
                for (int kk = 0; kk < 32; kk += 8) {
                    float av[2][4];
                    #pragma unroll
                    for (int m = 0; m < 2; m++) {
                        const float* xr = xs + (rbase + m*16)*XS_STRIDE + kk + tig;
                        av[m][0] = xr[ gid      * XS_STRIDE    ];
                        av[m][1] = xr[(gid + 8) * XS_STRIDE    ];
                        av[m][2] = xr[ gid      * XS_STRIDE + 4];
                        av[m][3] = xr[(gid + 8) * XS_STRIDE + 4];
                    }
                    if (cg == 0) {   /* colgroup 0 also owns x^2 for its rows */
                        x2r[0] = fmaf(av[0][0], av[0][0], fmaf(av[0][2], av[0][2], x2r[0]));
                        x2r[1] = fmaf(av[0][1], av[0][1], fmaf(av[0][3], av[0][3], x2r[1]));
                        x2r[2] = fmaf(av[1][0], av[1][0], fmaf(av[1][2], av[1][2], x2r[2]));
                        x2r[3] = fmaf(av[1][1], av[1][1], fmaf(av[1][3], av[1][3], x2r[3]));
                    }
                    uint32_t A[2][4];
                    #pragma unroll
                    for (int m = 0; m < 2; m++)
                        #pragma unroll
                        for (int j = 0; j < 4; j++)
                            A[m][j] = tf32_bits(av[m][j]);
                    const float* Blo = Bs + (kk + tig    ) * NB + cg * 32 + gid;
                    const float* Bhi = Bs + (kk + tig + 4) * NB + cg * 32 + gid;
                    if (cg == 0) {
                        #pragma unroll
                        for (int nt = 0; nt < 4; nt++) {
                            uint32_t b0 = tf32_bits(Blo[nt*8]);
                            uint32_t b1 = tf32_bits(Bhi[nt*8]);
                            mma8(acc[nt][0], A[0][0],A[0][1],A[0][2],A[0][3], b0, b1);
                            mma8(acc[nt][1], A[1][0],A[1][1],A[1][2],A[1][3], b0, b1);
                        }
                    } else {
                        #pragma unroll
                        for (int nt = 0; nt < 5; nt++) {
                            uint32_t b0 = tf32_bits(Blo[nt*8]);
                            uint32_t b1 = tf32_bits(Bhi[nt*8]);
                            mma8(acc[nt][0], A[0][0],A[0][1],A[0][2],A[0][3], b0, b1);
                            mma8(acc[nt][1], A[1][0],A[1][1],A[1][2],A[1][3], b0, b1);
                        }
                    }
                }
            }
        }
        __syncthreads();   /* all mainloop smem reads done before ep writes */

        /* reduce x^2 across the 4 tig lanes (colgroup-0 warps own rows) */
        if (cg == 0) {
            #pragma unroll
            for (int j = 0; j < 4; j++) {
                x2r[j] += __shfl_xor_sync(0xffffffffu, x2r[j], 1);
                x2r[j] += __shfl_xor_sync(0xffffffffu, x2r[j], 2);
            }
            if (tig == 0) {
                x2p[rbase + gid     ] = x2r[0];
                x2p[rbase + gid + 8 ] = x2r[1];
                x2p[rbase + gid + 16] = x2r[2];
                x2p[rbase + gid + 24] = x2r[3];
            }
        }

        /* stash accumulators into smem epilogue tile */
        {
            const int NT = (cg == 0) ? 4 : 5;
            const int cbase = cg * 32;
            #pragma unroll
            for (int nt = 0; nt < 5; nt++) {
                if (nt >= NT) break;
                #pragma unroll
                for (int m = 0; m < 2; m++) {
                    int r0 = rbase + m*16 + gid;
                    int c0 = cbase + nt*8 + 2*tig;
                    ep[ r0      * EP_STRIDE + c0    ] = acc[nt][m][0];
                    ep[ r0      * EP_STRIDE + c0 + 1] = acc[nt][m][1];
                    ep[(r0 + 8) * EP_STRIDE + c0    ] = acc[nt][m][2];
                    ep[(r0 + 8) * EP_STRIDE + c0 + 1] = acc[nt][m][3];
                }
            }
        }
        __syncthreads();
        /* vectorized relu(+bias) store to both output copies */
        {
            const int cb = (t & 1) * 32;
            #pragma unroll
            for (int i = 0; i < 8; i++) {
                int c = cb + 4 * i;
                float4 v = *(const float4*)(ep + lrow * EP_STRIDE + c);
                float4 b = *(const float4*)(b_pre + c);
                v.x = fmaxf(v.x + b.x, 0.f); v.y = fmaxf(v.y + b.y, 0.f);
                v.z = fmaxf(v.z + b.z, 0.f); v.w = fmaxf(v.w + b.w, 0.f);
                size_t go = (size_t)(rowBase + lrow) * 64 + c;
                *(float4*)(O1 + go) = v;
                *(float4*)(O2 + go) = v;
            }
        }
        /* hard assignment: softmax(1e7/dist) > 0.5  <=>  s < 2 at argmax */
        if (t < 128) {
            float x2 = x2p[t];
            float z[8], m = -3.4e38f;
            #pragma unroll
            for (int k = 0; k < 8; k++) {
                float dot = ep[t * EP_STRIDE + 64 + k];
                float d2  = fmaxf(x2 + c2s[k] - 2.0f * dot, 0.0f);
                float zk  = 1e7f / sqrtf(d2);
                z[k] = zk; m = fmaxf(m, zk);
            }
            float s = 0.f; int am = 0;
            #pragma unroll
            for (int k = 0; k < 8; k++) { s += expf(z[k] - m); if (z[k] == m) am = k; }
            sAssign[t] = (s < 2.0f) ? (unsigned char)am : (unsigned char)255;
        }
        __syncthreads();

        /* ---- fused cluster pooling: per-warp predicated reg partials ---- */
        const int nSeg0 = rowBase / P_PATCH;
        const int nSeg1 = (rowBase + M_TILE - 1) / P_PATCH;
        for (int seg = nSeg0; seg <= nSeg1; seg++) {
            const int lo = seg * P_PATCH, hi = lo + P_PATCH;
            #pragma unroll
            for (int cp = 0; cp < 2; cp++) {
                const int col = cp * 32 + lane;
                const float bias = b_pre[col];
                float pa[8];
                #pragma unroll
                for (int k = 0; k < 8; k++) pa[k] = 0.f;
                int cntMine = 0;
                #pragma unroll
                for (int i = 0; i < 16; i++) {
                    const int lr = wrow + i;
                    const int gr = rowBase + lr;
                    int a = (gr >= lo && gr < hi) ? (int)sAssign[lr] : 255;
                    float v = fmaxf(ep[lr * EP_STRIDE + col] + bias, 0.f);
                    #pragma unroll
                    for (int k = 0; k < 8; k++) pa[k] += (a == k) ? v : 0.f;
                    cntMine += (a == lane) ? 1 : 0;
                }
                #pragma unroll
                for (int k = 0; k < 8; k++) part[(warp*8 + k)*32 + lane] = pa[k];
                if (cp == 0 && lane < 8 && cntMine > 0)
                    atomicAdd(&g_counts[seg * 8 + lane], cntMine);
                __syncthreads();
                {
                    const int kk = t >> 5, cc = t & 31;
                    float s = 0.f;
                    #pragma unroll
                    for (int w = 0; w < 8; w++) s += part[(w*8 + kk)*32 + cc];
                    if (s != 0.f)
                        atomicAdd(&g_S[(seg * 8 + kk) * 64 + cp * 32 + cc], s);
                }
                __syncthreads();
            }
        }
    }
    /* =================== end persistent tile loop =================== */

    /* ---- tail handshake: last CTA runs the attention-MLP epilogue ---- */
    if (t == 0) {
        __threadfence();
        int old = atomicAdd(&g_done, 1);
        sLast = (old == GRID1 - 1);
    }
    __syncthreads();
    if (!sLast) return;

    __threadfence();   /* acquire: all CTAs' g_S/g_counts atomics visible */
    float* sA   = part;        /* [32] attention logits */
    float* pool = part + 32;   /* [4][64] pooled */

    /* phase 1: 8 warps x 4 (n,k) pairs each */
    for (int pi = 0; pi < 4; pi++) {
        const int p = warp + 8 * pi;
        int cnt = g_counts[p];
        float inv = cnt > 0 ? 1.0f / (float)cnt : 0.0f;
        const float* S = g_S + p * 64;
        float h0 = b_a1[lane], h1 = 0.f, h2 = 0.f, h3 = 0.f;
        #pragma unroll
        for (int d = 0; d < 64; d += 4) {
            h0 = fmaf(S[d    ] * inv, W_a1[(d    ) * 32 + lane], h0);
            h1 = fmaf(S[d + 1] * inv, W_a1[(d + 1) * 32 + lane], h1);
            h2 = fmaf(S[d + 2] * inv, W_a1[(d + 2) * 32 + lane], h2);
            h3 = fmaf(S[d + 3] * inv, W_a1[(d + 3) * 32 + lane], h3);
        }
        float h = tanhf((h0 + h1) + (h2 + h3));
        float c = h * W_a2[lane];
        #pragma unroll
        for (int o = 16; o; o >>= 1) c += __shfl_xor_sync(0xffffffffu, c, o);
        if (lane == 0) sA[p] = (cnt > 0) ? (c + b_a2[0]) : -100000.0f;
    }
    __syncthreads();

    /* phase 2: warps 0..3 -> softmax + pooling + proj_out for bag n */
    if (warp < 4) {
        const int n = warp;
        float m = -3.4e38f;
        #pragma unroll
        for (int k = 0; k < 8; k++) m = fmaxf(m, sA[n * 8 + k]);
        float e[8], s = 0.f;
        #pragma unroll
        for (int k = 0; k < 8; k++) { e[k] = expf(sA[n * 8 + k] - m); s += e[k]; }
        float p0 = 0.f, p1 = 0.f;
        #pragma unroll
        for (int k = 0; k < 8; k++) {
            int cnt = g_counts[n * 8 + k];
            float inv = cnt > 0 ? 1.0f / (float)cnt : 0.0f;
            float wgt = (e[k] / s) * inv;
            p0 = fmaf(g_S[(n * 8 + k) * 64 + lane     ], wgt, p0);
            p1 = fmaf(g_S[(n * 8 + k) * 64 + lane + 32], wgt, p1);
        }
        pool[n * 64 + lane] = p0; pool[n * 64 + lane + 32] = p1;
        __syncwarp();
        float ec = b_out[lane];
        #pragma unroll
        for (int d = 0; d < 64; d++) ec = fmaf(pool[n * 64 + d], W_out[d * 32 + lane], ec);
        out[n * 32 + lane] = fmaxf(ec, 0.f);
    }

    /* phase 3: reset scratch for next invocation */
    __syncthreads();
    #pragma unroll
    for (int j = 0; j < 8; j++) g_S[t + 256 * j] = 0.f;
    if (t < 32) g_counts[t] = 0;
    if (t == 0) { g_done = 0; g_next = 0; }
}

/* ------------------------------------------------------------------ */
extern "C" void kernel_launch(void* const* d_in, const int* in_sizes, int n_in,
                              void* d_out, int out_size)
{
    const float* x         = (const float*)d_in[0];
    const float* centroids = (const float*)d_in[1];
    const float* W_pre     = (const float*)d_in[2];
    const float* b_pre     = (const float*)d_in[3];
    const float* W_a1      = (const float*)d_in[4];
    const float* b_a1      = (const float*)d_in[5];
    const float* W_a2      = (const float*)d_in[6];
    const float* b_a2      = (const float*)d_in[7];
    const float* W_out     = (const float*)d_in[8];
    const float* b_out     = (const float*)d_in[9];

    float* out = (float*)d_out;
    float* O1 = out + 128;                         /* enc_seq copy 1 */
    float* O2 = out + 128 + (size_t)ROWS * 64;     /* enc_seq copy 2 */

    cudaFuncSetAttribute(k1, cudaFuncAttributeMaxDynamicSharedMemorySize, SMEM_BYTES);
    k1<<<GRID1, 256, SMEM_BYTES>>>(x, centroids, W_pre, b_pre,
                                   W_a1, b_a1, W_a2, b_a2, W_out, b_out,
                                   O1, O2, out);
}

// round 16
// speedup vs baseline: 1.1466x; 1.1466x over previous
#include <cuda_runtime.h>
#include <cstdint>

#define N_BAGS 4
#define P_PATCH 20000
#define DIN 1024
#define ROWS (N_BAGS*P_PATCH)   /* 80000 */
#define M_TILE 64
#define NTILES (ROWS/M_TILE)    /* 1250, exact */
#define GRID1 608               /* 4 CTAs/SM x 152 SMs: persistent */
#define NB 72                   /* 64 proj cols + 8 centroid cols */
#define XS_STRIDE 36
#define EP_STRIDE 76
#define BUF_FLOATS (M_TILE*XS_STRIDE + 32*NB)   /* 2304 + 2304 = 4608 */
/* buffers | x2p(64) c2s(8) sAssign(64B=16 floats) */
#define SMEM_FLOATS (2*BUF_FLOATS + 64 + 8 + 16)
#define SMEM_BYTES (SMEM_FLOATS * 4)            /* 37216 */

/* scratch (no allocation allowed). Zero at module load; the tail epilogue
   re-zeroes everything dirtied, so each call sees zeros (invariant). */
__device__ float g_S[32*64];
__device__ int   g_counts[32];
__device__ int   g_done;
__device__ int   g_next;

static __device__ __forceinline__ uint32_t tf32_bits(float f){
    uint32_t u; asm("cvt.rna.tf32.f32 %0, %1;" : "=r"(u) : "f"(f)); return u;
}

static __device__ __forceinline__ void mma8(float* c,
    uint32_t a0, uint32_t a1, uint32_t a2, uint32_t a3, uint32_t b0, uint32_t b1)
{
    asm volatile(
      "mma.sync.aligned.m16n8k8.row.col.f32.tf32.tf32.f32 "
      "{%0,%1,%2,%3},{%4,%5,%6,%7},{%8,%9},{%0,%1,%2,%3};\n"
      : "+f"(c[0]), "+f"(c[1]), "+f"(c[2]), "+f"(c[3])
      : "r"(a0), "r"(a1), "r"(a2), "r"(a3), "r"(b0), "r"(b1));
}

static __device__ __forceinline__ void cpa16(float* dst, const float* src){
    uint32_t d = (uint32_t)__cvta_generic_to_shared(dst);
    asm volatile("cp.async.cg.shared.global [%0], [%1], 16;\n" :: "r"(d), "l"(src));
}
static __device__ __forceinline__ void cpa4(float* dst, const float* src){
    uint32_t d = (uint32_t)__cvta_generic_to_shared(dst);
    asm volatile("cp.async.ca.shared.global [%0], [%1], 4;\n" :: "r"(d), "l"(src));
}
#define CP_COMMIT   asm volatile("cp.async.commit_group;\n" ::: "memory")
#define CP_WAIT1    asm volatile("cp.async.wait_group 1;\n" ::: "memory")
#define CP_WAIT0    asm volatile("cp.async.wait_group 0;\n" ::: "memory")

/* ------------------------------------------------------------------ */
/* Persistent kernel, M_TILE=64, 4 CTAs/SM. Per tile: cp.async double */
/* buffered xp = relu(x@Wpre+b) (dual store), hard assignment, fused  */
/* cluster pooling. Warp grid: 4 rowgroups(16 rows) x 2 colgroups.    */
/* Last CTA to finish runs the attention-MLP tail inline.             */
/* ------------------------------------------------------------------ */
__global__ __launch_bounds__(256, 4) void k1(
    const float* __restrict__ x, const float* __restrict__ centroids,
    const float* __restrict__ W_pre, const float* __restrict__ b_pre,
    const float* __restrict__ W_a1, const float* __restrict__ b_a1,
    const float* __restrict__ W_a2, const float* __restrict__ b_a2,
    const float* __restrict__ W_out, const float* __restrict__ b_out,
    float* __restrict__ O1, float* __restrict__ O2, float* __restrict__ out)
{
    extern __shared__ float sp[];
    float* ep   = sp;                       /* [64][76]=4864 epilogue (aliases bufs) */
    float* part = sp + 4864;                /* [8][8][32]=2048 pooling (aliases buf1) */
    float* x2p  = sp + 2*BUF_FLOATS;        /* [64] per-row x^2 (outside bufs) */
    float* c2s  = x2p + 64;                 /* [8] centroid norms */
    unsigned char* sAssign = (unsigned char*)(c2s + 8);  /* [64] bytes */
    __shared__ int sTile, sLast;

    const int t = threadIdx.x, warp = t >> 5, lane = t & 31;
    const int gid = lane >> 2, tig = lane & 3;
    const int rg = warp >> 1, cg = warp & 1;   /* 4 rowgroups x 2 colgroups */
    const int rbase = rg * 16;
    const int xr0 = t >> 3, xc0 = (t & 7) * 4; /* x staging: rows xr0, xr0+32 */
    const int wrow = warp * 8;                 /* pooling: 8 rows per warp */

    /* exact fp32 centroid norms (once per CTA): warp w -> centroid w */
    {
        float s = 0.f;
        const float* c = centroids + (size_t)warp * DIN;
        #pragma unroll
        for (int d = 0; d < DIN/32; d++) { float v = c[lane + 32*d]; s = fmaf(v, v, s); }
        #pragma unroll
        for (int o = 16; o; o >>= 1) s += __shfl_xor_sync(0xffffffffu, s, o);
        if (lane == 0) c2s[warp] = s;
    }

    const float* cg0c = centroids + (size_t)warp * DIN + lane;

    /* =================== persistent tile loop =================== */
    for (;;) {
        if (t == 0) sTile = atomicAdd(&g_next, 1);
        __syncthreads();
        const int tile = sTile;
        if (tile >= NTILES) break;
        const int rowBase = tile * M_TILE;

        float acc[5][4];
        #pragma unroll
        for (int nt = 0; nt < 5; nt++)
            acc[nt][0]=acc[nt][1]=acc[nt][2]=acc[nt][3]=0.f;
        float x2a = 0.f, x2b = 0.f;

        const float* xgA = x + (size_t)(rowBase + xr0) * DIN + xc0;
        const float* xgB = xgA + (size_t)32 * DIN;

        /* prefetch chunk 0 into buffer 0 */
        {
            float* xs = sp, * Bs = sp + M_TILE*XS_STRIDE;
            cpa16(xs +  xr0      * XS_STRIDE + xc0, xgA);
            cpa16(xs + (xr0 + 32)* XS_STRIDE + xc0, xgB);
            #pragma unroll
            for (int j = 0; j < 2; j++) {
                int idx = t + 256*j, r = idx >> 4, c4 = idx & 15;
                cpa16(Bs + r*NB + c4*4, W_pre + (size_t)r*64 + c4*4);
            }
            cpa4(Bs + lane*NB + 64 + warp, cg0c);
            CP_COMMIT;
        }

        #pragma unroll 1
        for (int i = 0; i < 32; i++) {
            if (i < 31) {   /* prefetch chunk i+1 into the other buffer */
                const int kcEl = (i + 1) * 32;
                float* xs = sp + ((i+1)&1)*BUF_FLOATS, * Bs = xs + M_TILE*XS_STRIDE;
                cpa16(xs +  xr0      * XS_STRIDE + xc0, xgA + kcEl);
                cpa16(xs + (xr0 + 32)* XS_STRIDE + xc0, xgB + kcEl);
                #pragma unroll
                for (int j = 0; j < 2; j++) {
                    int idx = t + 256*j, r = idx >> 4, c4 = idx & 15;
                    cpa16(Bs + r*NB + c4*4, W_pre + (size_t)(kcEl + r)*64 + c4*4);
                }
                cpa4(Bs + lane*NB + 64 + warp, cg0c + kcEl);
                CP_COMMIT;
                CP_WAIT1;
            } else {
                CP_WAIT0;
            }
            __syncthreads();
            /* MMA on buffer i&1: warp = 16 rows x colgroup (32/40 cols) */
            {
                const float* xs = sp + (i&1)*BUF_FLOATS;
                const float* Bs = xs + M_TILE*XS_STRIDE;
                #pragma unroll
                for (int kk = 0; kk < 32; kk += 8) {
                    const float* xr = xs + (rbase + gid) * XS_STRIDE + kk + tig;
                    float a0 = xr[0];
                    float a1 = xr[8 * XS_STRIDE];
                    float a2 = xr[4];
                    float a3 = xr[8 * XS_STRIDE + 4];
                    if (cg == 0) {
                        x2a = fmaf(a0, a0, fmaf(a2, a2, x2a));
                        x2b = fmaf(a1, a1, fmaf(a3, a3, x2b));
                    }
                    uint32_t A0 = tf32_bits(a0), A1 = tf32_bits(a1);
                    uint32_t A2 = tf32_bits(a2), A3 = tf32_bits(a3);
                    const float* Blo = Bs + (kk + tig    ) * NB + cg * 32 + gid;
                    const float* Bhi = Bs + (kk + tig + 4) * NB + cg * 32 + gid;
                    if (cg == 0) {
                        #pragma unroll
                        for (int nt = 0; nt < 4; nt++) {
                            uint32_t b0 = tf32_bits(Blo[nt*8]);
                            uint32_t b1 = tf32_bits(Bhi[nt*8]);
                            mma8(acc[nt], A0, A1, A2, A3, b0, b1);
                        }
                    } else {
                        #pragma unroll
                        for (int nt = 0; nt < 5; nt++) {
                            uint32_t b0 = tf32_bits(Blo[nt*8]);
                            uint32_t b1 = tf32_bits(Bhi[nt*8]);
                            mma8(acc[nt], A0, A1, A2, A3, b0, b1);
                        }
                    }
                }
            }
            __syncthreads();
        }

        /* reduce x^2 across the 4 tig lanes (colgroup-0 warps own rows) */
        if (cg == 0) {
            x2a += __shfl_xor_sync(0xffffffffu, x2a, 1);
            x2a += __shfl_xor_sync(0xffffffffu, x2a, 2);
            x2b += __shfl_xor_sync(0xffffffffu, x2b, 1);
            x2b += __shfl_xor_sync(0xffffffffu, x2b, 2);
            if (tig == 0) { x2p[rbase + gid] = x2a; x2p[rbase + gid + 8] = x2b; }
        }

        /* stash accumulators into smem epilogue tile */
        {
            const int NT = (cg == 0) ? 4 : 5;
            const int cbase = cg * 32;
            #pragma unroll
            for (int nt = 0; nt < 5; nt++) {
                if (nt >= NT) break;
                int c0 = cbase + nt*8 + 2*tig;
                ep[(rbase + gid    ) * EP_STRIDE + c0    ] = acc[nt][0];
                ep[(rbase + gid    ) * EP_STRIDE + c0 + 1] = acc[nt][1];
                ep[(rbase + gid + 8) * EP_STRIDE + c0    ] = acc[nt][2];
                ep[(rbase + gid + 8) * EP_STRIDE + c0 + 1] = acc[nt][3];
            }
        }
        __syncthreads();
        /* vectorized relu(+bias) store to both output copies */
        {
            const int lrow = t >> 2, cb = (t & 3) * 16;
            #pragma unroll
            for (int i = 0; i < 4; i++) {
                int c = cb + 4 * i;
                float4 v = *(const float4*)(ep + lrow * EP_STRIDE + c);
                float4 b = *(const float4*)(b_pre + c);
                v.x = fmaxf(v.x + b.x, 0.f); v.y = fmaxf(v.y + b.y, 0.f);
                v.z = fmaxf(v.z + b.z, 0.f); v.w = fmaxf(v.w + b.w, 0.f);
                size_t go = (size_t)(rowBase + lrow) * 64 + c;
                *(float4*)(O1 + go) = v;
                *(float4*)(O2 + go) = v;
            }
        }
        /* hard assignment: softmax(1e7/dist) > 0.5  <=>  s < 2 at argmax */
        if (t < 64) {
            float x2 = x2p[t];
            float z[8], m = -3.4e38f;
            #pragma unroll
            for (int k = 0; k < 8; k++) {
                float dot = ep[t * EP_STRIDE + 64 + k];
                float d2  = fmaxf(x2 + c2s[k] - 2.0f * dot, 0.0f);
                float zk  = 1e7f / sqrtf(d2);
                z[k] = zk; m = fmaxf(m, zk);
            }
            float s = 0.f; int am = 0;
            #pragma unroll
            for (int k = 0; k < 8; k++) { s += expf(z[k] - m); if (z[k] == m) am = k; }
            sAssign[t] = (s < 2.0f) ? (unsigned char)am : (unsigned char)255;
        }
        __syncthreads();

        /* ---- fused cluster pooling: per-warp predicated reg partials ---- */
        const int nSeg0 = rowBase / P_PATCH;
        const int nSeg1 = (rowBase + M_TILE - 1) / P_PATCH;
        for (int seg = nSeg0; seg <= nSeg1; seg++) {
            const int lo = seg * P_PATCH, hi = lo + P_PATCH;
            #pragma unroll
            for (int cp = 0; cp < 2; cp++) {
                const int col = cp * 32 + lane;
                const float bias = b_pre[col];
                float pa[8];
                #pragma unroll
                for (int k = 0; k < 8; k++) pa[k] = 0.f;
                int cntMine = 0;
                #pragma unroll
                for (int i = 0; i < 8; i++) {
                    const int lr = wrow + i;
                    const int gr = rowBase + lr;
                    int a = (gr >= lo && gr < hi) ? (int)sAssign[lr] : 255;
                    float v = fmaxf(ep[lr * EP_STRIDE + col] + bias, 0.f);
                    #pragma unroll
                    for (int k = 0; k < 8; k++) pa[k] += (a == k) ? v : 0.f;
                    cntMine += (a == lane) ? 1 : 0;
                }
                #pragma unroll
                for (int k = 0; k < 8; k++) part[(warp*8 + k)*32 + lane] = pa[k];
                if (cp == 0 && lane < 8 && cntMine > 0)
                    atomicAdd(&g_counts[seg * 8 + lane], cntMine);
                __syncthreads();
                {
                    const int kk = t >> 5, cc = t & 31;
                    float s = 0.f;
                    #pragma unroll
                    for (int w = 0; w < 8; w++) s += part[(w*8 + kk)*32 + cc];
                    if (s != 0.f)
                        atomicAdd(&g_S[(seg * 8 + kk) * 64 + cp * 32 + cc], s);
                }
                __syncthreads();
            }
        }
    }
    /* =================== end persistent tile loop =================== */

    /* ---- tail handshake: last CTA runs the attention-MLP epilogue ---- */
    if (t == 0) {
        __threadfence();
        int old = atomicAdd(&g_done, 1);
        sLast = (old == GRID1 - 1);
    }
    __syncthreads();
    if (!sLast) return;

    __threadfence();   /* acquire: all CTAs' g_S/g_counts atomics visible */
    float* sA   = part;        /* [32] attention logits */
    float* pool = part + 32;   /* [4][64] pooled */

    /* phase 1: 8 warps x 4 (n,k) pairs each */
    for (int pi = 0; pi < 4; pi++) {
        const int p = warp + 8 * pi;
        int cnt = g_counts[p];
        float inv = cnt > 0 ? 1.0f / (float)cnt : 0.0f;
        const float* S = g_S + p * 64;
        float h0 = b_a1[lane], h1 = 0.f, h2 = 0.f, h3 = 0.f;
        #pragma unroll
        for (int d = 0; d < 64; d += 4) {
            h0 = fmaf(S[d    ] * inv, W_a1[(d    ) * 32 + lane], h0);
            h1 = fmaf(S[d + 1] * inv, W_a1[(d + 1) * 32 + lane], h1);
            h2 = fmaf(S[d + 2] * inv, W_a1[(d + 2) * 32 + lane], h2);
            h3 = fmaf(S[d + 3] * inv, W_a1[(d + 3) * 32 + lane], h3);
        }
        float h = tanhf((h0 + h1) + (h2 + h3));
        float c = h * W_a2[lane];
        #pragma unroll
        for (int o = 16; o; o >>= 1) c += __shfl_xor_sync(0xffffffffu, c, o);
        if (lane == 0) sA[p] = (cnt > 0) ? (c + b_a2[0]) : -100000.0f;
    }
    __syncthreads();

    /* phase 2: warps 0..3 -> softmax + pooling + proj_out for bag n */
    if (warp < 4) {
        const int n = warp;
        float m = -3.4e38f;
        #pragma unroll
        for (int k = 0; k < 8; k++) m = fmaxf(m, sA[n * 8 + k]);
        float e[8], s = 0.f;
        #pragma unroll
        for (int k = 0; k < 8; k++) { e[k] = expf(sA[n * 8 + k] - m); s += e[k]; }
        float p0 = 0.f, p1 = 0.f;
        #pragma unroll
        for (int k = 0; k < 8; k++) {
            int cnt = g_counts[n * 8 + k];
            float inv = cnt > 0 ? 1.0f / (float)cnt : 0.0f;
            float wgt = (e[k] / s) * inv;
            p0 = fmaf(g_S[(n * 8 + k) * 64 + lane     ], wgt, p0);
            p1 = fmaf(g_S[(n * 8 + k) * 64 + lane + 32], wgt, p1);
        }
        pool[n * 64 + lane] = p0; pool[n * 64 + lane + 32] = p1;
        __syncwarp();
        float ec = b_out[lane];
        #pragma unroll
        for (int d = 0; d < 64; d++) ec = fmaf(pool[n * 64 + d], W_out[d * 32 + lane], ec);
        out[n * 32 + lane] = fmaxf(ec, 0.f);
    }

    /* phase 3: reset scratch for next invocation */
    __syncthreads();
    #pragma unroll
    for (int j = 0; j < 8; j++) g_S[t + 256 * j] = 0.f;
    if (t < 32) g_counts[t] = 0;
    if (t == 0) { g_done = 0; g_next = 0; }
}

/* ------------------------------------------------------------------ */
extern "C" void kernel_launch(void* const* d_in, const int* in_sizes, int n_in,
                              void* d_out, int out_size)
{
    const float* x         = (const float*)d_in[0];
    const float* centroids = (const float*)d_in[1];
    const float* W_pre     = (const float*)d_in[2];
    const float* b_pre     = (const float*)d_in[3];
    const float* W_a1      = (const float*)d_in[4];
    const float* b_a1      = (const float*)d_in[5];
    const float* W_a2      = (const float*)d_in[6];
    const float* b_a2      = (const float*)d_in[7];
    const float* W_out     = (const float*)d_in[8];
    const float* b_out     = (const float*)d_in[9];

    float* out = (float*)d_out;
    float* O1 = out + 128;                         /* enc_seq copy 1 */
    float* O2 = out + 128 + (size_t)ROWS * 64;     /* enc_seq copy 2 */

    cudaFuncSetAttribute(k1, cudaFuncAttributeMaxDynamicSharedMemorySize, SMEM_BYTES);
    k1<<<GRID1, 256, SMEM_BYTES>>>(x, centroids, W_pre, b_pre,
                                   W_a1, b_a1, W_a2, b_a2, W_out, b_out,
                                   O1, O2, out);
}

// round 17
// speedup vs baseline: 1.2848x; 1.1206x over previous
#include <cuda_runtime.h>
#include <cstdint>

#define N_BAGS 4
#define P_PATCH 20000
#define DIN 1024
#define ROWS (N_BAGS*P_PATCH)   /* 80000 */
#define M_TILE 64
#define NTILES (ROWS/M_TILE)    /* 1250, exact */
#define GRID1 608               /* 4 CTAs/SM x 152 SMs: persistent */
#define NB 72                   /* 64 proj cols + 8 centroid cols */
#define XS_STRIDE 36
#define EP_STRIDE 76
#define B_CHUNK (32*NB)         /* 2304 floats per chunk, SAME layout as smem */
#define BUF_FLOATS (M_TILE*XS_STRIDE + B_CHUNK)   /* 2304 + 2304 = 4608 */
/* buffers | x2p(64) c2s(8) sAssign(64B=16 floats) */
#define SMEM_FLOATS (2*BUF_FLOATS + 64 + 8 + 16)
#define SMEM_BYTES (SMEM_FLOATS * 4)            /* 37216 */

/* scratch (no allocation allowed). Zero at module load; the tail epilogue
   re-zeroes everything dirtied, so each call sees zeros (invariant). */
__device__ float g_S[32*64];
__device__ int   g_counts[32];
__device__ int   g_done;
__device__ float g_Btf[32*B_CHUNK];  /* tf32-rounded [W_pre | centroids^T] */
__device__ int   g_next;

static __device__ __forceinline__ uint32_t tf32_bits(float f){
    uint32_t u; asm("cvt.rna.tf32.f32 %0, %1;" : "=r"(u) : "f"(f)); return u;
}

static __device__ __forceinline__ void mma8(float* c,
    uint32_t a0, uint32_t a1, uint32_t a2, uint32_t a3, uint32_t b0, uint32_t b1)
{
    asm volatile(
      "mma.sync.aligned.m16n8k8.row.col.f32.tf32.tf32.f32 "
      "{%0,%1,%2,%3},{%4,%5,%6,%7},{%8,%9},{%0,%1,%2,%3};\n"
      : "+f"(c[0]), "+f"(c[1]), "+f"(c[2]), "+f"(c[3])
      : "r"(a0), "r"(a1), "r"(a2), "r"(a3), "r"(b0), "r"(b1));
}

static __device__ __forceinline__ void cpa16(float* dst, const float* src){
    uint32_t d = (uint32_t)__cvta_generic_to_shared(dst);
    asm volatile("cp.async.cg.shared.global [%0], [%1], 16;\n" :: "r"(d), "l"(src));
}
#define CP_COMMIT   asm volatile("cp.async.commit_group;\n" ::: "memory")
#define CP_WAIT1    asm volatile("cp.async.wait_group 1;\n" ::: "memory")
#define CP_WAIT0    asm volatile("cp.async.wait_group 0;\n" ::: "memory")

/* ------------------------------------------------------------------ */
/* Kernel 0: one-shot tf32 conversion of B = [W_pre | centroids^T]    */
/* into g_Btf with the EXACT smem staging layout [chunk][32][72].     */
/* ------------------------------------------------------------------ */
__global__ __launch_bounds__(256) void k0(
    const float* __restrict__ W_pre, const float* __restrict__ centroids)
{
    int idx = blockIdx.x * 256 + threadIdx.x;
    for (int e = idx; e < 32*B_CHUNK; e += gridDim.x * 256) {
        int q = e / B_CHUNK, rem = e - q * B_CHUNK;
        int r = rem / NB, c = rem - r * NB;
        float v = (c < 64) ? W_pre[(size_t)(q*32 + r) * 64 + c]
                           : centroids[(size_t)(c - 64) * DIN + q*32 + r];
        g_Btf[e] = __uint_as_float(tf32_bits(v));
    }
}

/* ------------------------------------------------------------------ */
/* Persistent kernel, M_TILE=64, 4 CTAs/SM. Per tile: cp.async double */
/* buffered xp = relu(x@Wpre+b) (dual store), hard assignment, fused  */
/* cluster pooling. Warp grid: 4 rowgroups(16 rows) x 2 colgroups.    */
/* B staged pre-converted (zero B cvts in mainloop).                  */
/* Last CTA to finish runs the attention-MLP tail inline.             */
/* ------------------------------------------------------------------ */
__global__ __launch_bounds__(256, 4) void k1(
    const float* __restrict__ x, const float* __restrict__ centroids,
    const float* __restrict__ b_pre,
    const float* __restrict__ W_a1, const float* __restrict__ b_a1,
    const float* __restrict__ W_a2, const float* __restrict__ b_a2,
    const float* __restrict__ W_out, const float* __restrict__ b_out,
    float* __restrict__ O1, float* __restrict__ O2, float* __restrict__ out)
{
    extern __shared__ float sp[];
    float* ep   = sp;                       /* [64][76]=4864 epilogue (aliases bufs) */
    float* part = sp + 4864;                /* [8][8][32]=2048 pooling (aliases buf1) */
    float* x2p  = sp + 2*BUF_FLOATS;        /* [64] per-row x^2 (outside bufs) */
    float* c2s  = x2p + 64;                 /* [8] centroid norms */
    unsigned char* sAssign = (unsigned char*)(c2s + 8);  /* [64] bytes */
    __shared__ int sTile, sLast;

    const int t = threadIdx.x, warp = t >> 5, lane = t & 31;
    const int gid = lane >> 2, tig = lane & 3;
    const int rg = warp >> 1, cg = warp & 1;   /* 4 rowgroups x 2 colgroups */
    const int rbase = rg * 16;
    const int xr0 = t >> 3, xc0 = (t & 7) * 4; /* x staging: rows xr0, xr0+32 */
    const int wrow = warp * 8;                 /* pooling: 8 rows per warp */

    /* exact fp32 centroid norms (once per CTA): warp w -> centroid w */
    {
        float s = 0.f;
        const float* c = centroids + (size_t)warp * DIN;
        #pragma unroll
        for (int d = 0; d < DIN/32; d++) { float v = c[lane + 32*d]; s = fmaf(v, v, s); }
        #pragma unroll
        for (int o = 16; o; o >>= 1) s += __shfl_xor_sync(0xffffffffu, s, o);
        if (lane == 0) c2s[warp] = s;
    }

    /* =================== persistent tile loop =================== */
    for (;;) {
        if (t == 0) sTile = atomicAdd(&g_next, 1);
        __syncthreads();
        const int tile = sTile;
        if (tile >= NTILES) break;
        const int rowBase = tile * M_TILE;

        float acc[5][4];
        #pragma unroll
        for (int nt = 0; nt < 5; nt++)
            acc[nt][0]=acc[nt][1]=acc[nt][2]=acc[nt][3]=0.f;
        float x2a = 0.f, x2b = 0.f;

        const float* xgA = x + (size_t)(rowBase + xr0) * DIN + xc0;
        const float* xgB = xgA + (size_t)32 * DIN;

        /* prefetch chunk 0 into buffer 0 */
        {
            float* xs = sp, * Bs = sp + M_TILE*XS_STRIDE;
            cpa16(xs +  xr0      * XS_STRIDE + xc0, xgA);
            cpa16(xs + (xr0 + 32)* XS_STRIDE + xc0, xgB);
            cpa16(Bs + t*4,         g_Btf + t*4);
            cpa16(Bs + (t+256)*4,   g_Btf + (t+256)*4);
            if (t < 64) cpa16(Bs + (t+512)*4, g_Btf + (t+512)*4);
            CP_COMMIT;
        }

        #pragma unroll 1
        for (int i = 0; i < 32; i++) {
            if (i < 31) {   /* prefetch chunk i+1 into the other buffer */
                const int kcEl = (i + 1) * 32;
                float* xs = sp + ((i+1)&1)*BUF_FLOATS, * Bs = xs + M_TILE*XS_STRIDE;
                const float* bsrc = g_Btf + (i+1)*B_CHUNK;
                cpa16(xs +  xr0      * XS_STRIDE + xc0, xgA + kcEl);
                cpa16(xs + (xr0 + 32)* XS_STRIDE + xc0, xgB + kcEl);
                cpa16(Bs + t*4,         bsrc + t*4);
                cpa16(Bs + (t+256)*4,   bsrc + (t+256)*4);
                if (t < 64) cpa16(Bs + (t+512)*4, bsrc + (t+512)*4);
                CP_COMMIT;
                CP_WAIT1;
            } else {
                CP_WAIT0;
            }
            __syncthreads();
            /* MMA on buffer i&1: warp = 16 rows x colgroup (32/40 cols).
               B already tf32 -> raw bit reinterpret, zero cvts. */
            {
                const float* xs = sp + (i&1)*BUF_FLOATS;
                const float* Bs = xs + M_TILE*XS_STRIDE;
                #pragma unroll
                for (int kk = 0; kk < 32; kk += 8) {
                    const float* xr = xs + (rbase + gid) * XS_STRIDE + kk + tig;
                    float a0 = xr[0];
                    float a1 = xr[8 * XS_STRIDE];
                    float a2 = xr[4];
                    float a3 = xr[8 * XS_STRIDE + 4];
                    if (cg == 0) {
                        x2a = fmaf(a0, a0, fmaf(a2, a2, x2a));
                        x2b = fmaf(a1, a1, fmaf(a3, a3, x2b));
                    }
                    uint32_t A0 = tf32_bits(a0), A1 = tf32_bits(a1);
                    uint32_t A2 = tf32_bits(a2), A3 = tf32_bits(a3);
                    const float* Blo = Bs + (kk + tig    ) * NB + cg * 32 + gid;
                    const float* Bhi = Bs + (kk + tig + 4) * NB + cg * 32 + gid;
                    if (cg == 0) {
                        #pragma unroll
                        for (int nt = 0; nt < 4; nt++) {
                            uint32_t b0 = __float_as_uint(Blo[nt*8]);
                            uint32_t b1 = __float_as_uint(Bhi[nt*8]);
                            mma8(acc[nt], A0, A1, A2, A3, b0, b1);
                        }
                    } else {
                        #pragma unroll
                        for (int nt = 0; nt < 5; nt++) {
                            uint32_t b0 = __float_as_uint(Blo[nt*8]);
                            uint32_t b1 = __float_as_uint(Bhi[nt*8]);
                            mma8(acc[nt], A0, A1, A2, A3, b0, b1);
                        }
                    }
                }
            }
            __syncthreads();
        }

        /* reduce x^2 across the 4 tig lanes (colgroup-0 warps own rows) */
        if (cg == 0) {
            x2a += __shfl_xor_sync(0xffffffffu, x2a, 1);
            x2a += __shfl_xor_sync(0xffffffffu, x2a, 2);
            x2b += __shfl_xor_sync(0xffffffffu, x2b, 1);
            x2b += __shfl_xor_sync(0xffffffffu, x2b, 2);
            if (tig == 0) { x2p[rbase + gid] = x2a; x2p[rbase + gid + 8] = x2b; }
        }

        /* stash accumulators into smem epilogue tile */
        {
            const int NT = (cg == 0) ? 4 : 5;
            const int cbase = cg * 32;
            #pragma unroll
            for (int nt = 0; nt < 5; nt++) {
                if (nt >= NT) break;
                int c0 = cbase + nt*8 + 2*tig;
                ep[(rbase + gid    ) * EP_STRIDE + c0    ] = acc[nt][0];
                ep[(rbase + gid    ) * EP_STRIDE + c0 + 1] = acc[nt][1];
                ep[(rbase + gid + 8) * EP_STRIDE + c0    ] = acc[nt][2];
                ep[(rbase + gid + 8) * EP_STRIDE + c0 + 1] = acc[nt][3];
            }
        }
        __syncthreads();
        /* vectorized relu(+bias) store to both output copies */
        {
            const int lrow = t >> 2, cb = (t & 3) * 16;
            #pragma unroll
            for (int i = 0; i < 4; i++) {
                int c = cb + 4 * i;
                float4 v = *(const float4*)(ep + lrow * EP_STRIDE + c);
                float4 b = *(const float4*)(b_pre + c);
                v.x = fmaxf(v.x + b.x, 0.f); v.y = fmaxf(v.y + b.y, 0.f);
                v.z = fmaxf(v.z + b.z, 0.f); v.w = fmaxf(v.w + b.w, 0.f);
                size_t go = (size_t)(rowBase + lrow) * 64 + c;
                *(float4*)(O1 + go) = v;
                *(float4*)(O2 + go) = v;
            }
        }
        /* hard assignment: softmax(1e7/dist) > 0.5  <=>  s < 2 at argmax */
        if (t < 64) {
            float x2 = x2p[t];
            float z[8], m = -3.4e38f;
            #pragma unroll
            for (int k = 0; k < 8; k++) {
                float dot = ep[t * EP_STRIDE + 64 + k];
                float d2  = fmaxf(x2 + c2s[k] - 2.0f * dot, 0.0f);
                float zk  = 1e7f / sqrtf(d2);
                z[k] = zk; m = fmaxf(m, zk);
            }
            float s = 0.f; int am = 0;
            #pragma unroll
            for (int k = 0; k < 8; k++) { s += expf(z[k] - m); if (z[k] == m) am = k; }
            sAssign[t] = (s < 2.0f) ? (unsigned char)am : (unsigned char)255;
        }
        __syncthreads();

        /* ---- fused cluster pooling: per-warp predicated reg partials ---- */
        const int nSeg0 = rowBase / P_PATCH;
        const int nSeg1 = (rowBase + M_TILE - 1) / P_PATCH;
        for (int seg = nSeg0; seg <= nSeg1; seg++) {
            const int lo = seg * P_PATCH, hi = lo + P_PATCH;
            #pragma unroll
            for (int cp = 0; cp < 2; cp++) {
                const int col = cp * 32 + lane;
                const float bias = b_pre[col];
                float pa[8];
                #pragma unroll
                for (int k = 0; k < 8; k++) pa[k] = 0.f;
                int cntMine = 0;
                #pragma unroll
                for (int i = 0; i < 8; i++) {
                    const int lr = wrow + i;
                    const int gr = rowBase + lr;
                    int a = (gr >= lo && gr < hi) ? (int)sAssign[lr] : 255;
                    float v = fmaxf(ep[lr * EP_STRIDE + col] + bias, 0.f);
                    #pragma unroll
                    for (int k = 0; k < 8; k++) pa[k] += (a == k) ? v : 0.f;
                    cntMine += (a == lane) ? 1 : 0;
                }
                #pragma unroll
                for (int k = 0; k < 8; k++) part[(warp*8 + k)*32 + lane] = pa[k];
                if (cp == 0 && lane < 8 && cntMine > 0)
                    atomicAdd(&g_counts[seg * 8 + lane], cntMine);
                __syncthreads();
                {
                    const int kk = t >> 5, cc = t & 31;
                    float s = 0.f;
                    #pragma unroll
                    for (int w = 0; w < 8; w++) s += part[(w*8 + kk)*32 + cc];
                    if (s != 0.f)
                        atomicAdd(&g_S[(seg * 8 + kk) * 64 + cp * 32 + cc], s);
                }
                __syncthreads();
            }
        }
    }
    /* =================== end persistent tile loop =================== */

    /* ---- tail handshake: last CTA runs the attention-MLP epilogue ---- */
    if (t == 0) {
        __threadfence();
        int old = atomicAdd(&g_done, 1);
        sLast = (old == GRID1 - 1);
    }
    __syncthreads();
    if (!sLast) return;

    __threadfence();   /* acquire: all CTAs' g_S/g_counts atomics visible */
    float* sA   = part;        /* [32] attention logits */
    float* pool = part + 32;   /* [4][64] pooled */

    /* phase 1: 8 warps x 4 (n,k) pairs each */
    for (int pi = 0; pi < 4; pi++) {
        const int p = warp + 8 * pi;
        int cnt = g_counts[p];
        float inv = cnt > 0 ? 1.0f / (float)cnt : 0.0f;
        const float* S = g_S + p * 64;
        float h0 = b_a1[lane], h1 = 0.f, h2 = 0.f, h3 = 0.f;
        #pragma unroll
        for (int d = 0; d < 64; d += 4) {
            h0 = fmaf(S[d    ] * inv, W_a1[(d    ) * 32 + lane], h0);
            h1 = fmaf(S[d + 1] * inv, W_a1[(d + 1) * 32 + lane], h1);
            h2 = fmaf(S[d + 2] * inv, W_a1[(d + 2) * 32 + lane], h2);
            h3 = fmaf(S[d + 3] * inv, W_a1[(d + 3) * 32 + lane], h3);
        }
        float h = tanhf((h0 + h1) + (h2 + h3));
        float c = h * W_a2[lane];
        #pragma unroll
        for (int o = 16; o; o >>= 1) c += __shfl_xor_sync(0xffffffffu, c, o);
        if (lane == 0) sA[p] = (cnt > 0) ? (c + b_a2[0]) : -100000.0f;
    }
    __syncthreads();

    /* phase 2: warps 0..3 -> softmax + pooling + proj_out for bag n */
    if (warp < 4) {
        const int n = warp;
        float m = -3.4e38f;
        #pragma unroll
        for (int k = 0; k < 8; k++) m = fmaxf(m, sA[n * 8 + k]);
        float e[8], s = 0.f;
        #pragma unroll
        for (int k = 0; k < 8; k++) { e[k] = expf(sA[n * 8 + k] - m); s += e[k]; }
        float p0 = 0.f, p1 = 0.f;
        #pragma unroll
        for (int k = 0; k < 8; k++) {
            int cnt = g_counts[n * 8 + k];
            float inv = cnt > 0 ? 1.0f / (float)cnt : 0.0f;
            float wgt = (e[k] / s) * inv;
            p0 = fmaf(g_S[(n * 8 + k) * 64 + lane     ], wgt, p0);
            p1 = fmaf(g_S[(n * 8 + k) * 64 + lane + 32], wgt, p1);
        }
        pool[n * 64 + lane] = p0; pool[n * 64 + lane + 32] = p1;
        __syncwarp();
        float ec = b_out[lane];
        #pragma unroll
        for (int d = 0; d < 64; d++) ec = fmaf(pool[n * 64 + d], W_out[d * 32 + lane], ec);
        out[n * 32 + lane] = fmaxf(ec, 0.f);
    }

    /* phase 3: reset scratch for next invocation */
    __syncthreads();
    #pragma unroll
    for (int j = 0; j < 8; j++) g_S[t + 256 * j] = 0.f;
    if (t < 32) g_counts[t] = 0;
    if (t == 0) { g_done = 0; g_next = 0; }
}

/* ------------------------------------------------------------------ */
extern "C" void kernel_launch(void* const* d_in, const int* in_sizes, int n_in,
                              void* d_out, int out_size)
{
    const float* x         = (const float*)d_in[0];
    const float* centroids = (const float*)d_in[1];
    const float* W_pre     = (const float*)d_in[2];
    const float* b_pre     = (const float*)d_in[3];
    const float* W_a1      = (const float*)d_in[4];
    const float* b_a1      = (const float*)d_in[5];
    const float* W_a2      = (const float*)d_in[6];
    const float* b_a2      = (const float*)d_in[7];
    const float* W_out     = (const float*)d_in[8];
    const float* b_out     = (const float*)d_in[9];

    float* out = (float*)d_out;
    float* O1 = out + 128;                         /* enc_seq copy 1 */
    float* O2 = out + 128 + (size_t)ROWS * 64;     /* enc_seq copy 2 */

    cudaFuncSetAttribute(k1, cudaFuncAttributeMaxDynamicSharedMemorySize, SMEM_BYTES);
    k0<<<72, 256>>>(W_pre, centroids);
    k1<<<GRID1, 256, SMEM_BYTES>>>(x, centroids, b_pre,
                                   W_a1, b_a1, W_a2, b_a2, W_out, b_out,
                                   O1, O2, out);
}